// round 2
// baseline (speedup 1.0000x reference)
#include <cuda_runtime.h>

#define BATCH 4
#define CH    64
#define HH    128
#define WW    128
#define HW    (HH*WW)
#define K9    9
#define J18   18
#define CK    576   /* CH*K9 */

// Device-global scratch (no allocations allowed in kernel_launch)
__device__ float g_xt[BATCH*HW*CH];    // x transposed to [b][h][w][c]  (16 MB)
__device__ float g_off[BATCH*HW*J18];  // offsets [b][h][w][j]          (4.5 MB)
__device__ float g_wT[CK*CH];          // W_T[ck][o] = weight[o][c][k]  (147 KB)

// ---------------------------------------------------------------------------
// Transpose main weight: [o][c][k] -> [c*9+k][o]
// ---------------------------------------------------------------------------
__global__ void k_prep_wT(const float* __restrict__ weight) {
    int i = blockIdx.x * 256 + threadIdx.x;
    if (i >= CK * CH) return;
    int o  = i & 63;
    int ck = i >> 6;
    int c = ck / 9, k = ck % 9;
    g_wT[i] = weight[(o * CH + c) * 9 + k];
}

// ---------------------------------------------------------------------------
// NCHW -> NHWC transpose of x (per batch: [64][16384] -> [16384][64])
// ---------------------------------------------------------------------------
__global__ void k_transpose(const float* __restrict__ x) {
    __shared__ float t[32][33];
    int b  = blockIdx.z;
    int c0 = blockIdx.y * 32;
    int p0 = blockIdx.x * 32;
    int tx = threadIdx.x, ty = threadIdx.y;   // 32 x 8
    const float* xb = x + (size_t)b * CH * HW;
#pragma unroll
    for (int i = 0; i < 4; i++)
        t[ty + i * 8][tx] = xb[(c0 + ty + i * 8) * HW + p0 + tx];
    __syncthreads();
    float* dst = g_xt + (size_t)b * HW * CH;
#pragma unroll
    for (int i = 0; i < 4; i++)
        dst[(p0 + ty + i * 8) * CH + c0 + tx] = t[tx][ty + i * 8];
}

// ---------------------------------------------------------------------------
// Offset conv: Conv2d(64 -> 18, 3x3, pad 1) on NCHW x.
// Block (32,4): 32-wide x 4-tall tile. w_off staged transposed in smem as
// [c][tap][j padded to 20] so the inner j-loop is broadcast LDS.128.
// ---------------------------------------------------------------------------
__global__ void k_offconv(const float* __restrict__ x,
                          const float* __restrict__ w_off,
                          const float* __restrict__ b_off) {
    __shared__ __align__(16) float ws[CH * 9 * 20];   // 46080 B
    int tid = threadIdx.y * 32 + threadIdx.x;
    for (int i = tid; i < CH * 9 * J18; i += 128) {
        int j = i % 18; int t = i / 18; int tap = t % 9; int c = t / 9;
        ws[(c * 9 + tap) * 20 + j] = w_off[(j * CH + c) * 9 + tap];
    }
    __syncthreads();

    int b = blockIdx.z;
    int h = blockIdx.y * 4 + threadIdx.y;
    int w = blockIdx.x * 32 + threadIdx.x;

    float acc[18];
#pragma unroll
    for (int j = 0; j < 18; j++) acc[j] = __ldg(b_off + j);

    const float* xb = x + (size_t)b * CH * HW;
    for (int c = 0; c < CH; c++) {
        const float* xc = xb + c * HW;
#pragma unroll
        for (int r = 0; r < 3; r++) {
            int y = h + r - 1;
            if ((unsigned)y < (unsigned)HH) {
                const float* xr = xc + y * WW;
                float v0 = (w >= 1)      ? __ldg(xr + w - 1) : 0.f;
                float v1 =                 __ldg(xr + w);
                float v2 = (w < WW - 1)  ? __ldg(xr + w + 1) : 0.f;
                const float* wsr = ws + (c * 9 + r * 3) * 20;
#pragma unroll
                for (int s = 0; s < 3; s++) {
                    float val = (s == 0) ? v0 : ((s == 1) ? v1 : v2);
                    const float4* wp4 = (const float4*)(wsr + s * 20);
#pragma unroll
                    for (int q = 0; q < 4; q++) {
                        float4 wv = wp4[q];
                        acc[q * 4 + 0] += wv.x * val;
                        acc[q * 4 + 1] += wv.y * val;
                        acc[q * 4 + 2] += wv.z * val;
                        acc[q * 4 + 3] += wv.w * val;
                    }
                    acc[16] += (wsr + s * 20)[16] * val;
                    acc[17] += (wsr + s * 20)[17] * val;
                }
            }
        }
    }

    // Stage through smem, then write coalesced rows of 576 floats.
    __syncthreads();
#pragma unroll
    for (int j = 0; j < 18; j++)
        ws[threadIdx.y * 576 + threadIdx.x * 18 + j] = acc[j];
    __syncthreads();
    for (int i = tid; i < 4 * 576; i += 128) {
        int row = i / 576, col = i % 576;
        int h2 = blockIdx.y * 4 + row;
        g_off[((size_t)b * HW + h2 * WW + blockIdx.x * 32) * 18 + col] = ws[row * 576 + col];
    }
}

// ---------------------------------------------------------------------------
// Deformable gather + 64x576 contraction per 4x4 pixel tile.
// Phase 1: warp per (pixel, tap) task; lanes cover 64 channels via float2.
// Phase 2: thread = (o, pixel-group); W via coalesced LDG, S via broadcast LDS.
// ---------------------------------------------------------------------------
__global__ void k_deform(float* __restrict__ out) {
    __shared__ __align__(16) float s[16 * CK];   // 36864 B
    int b  = blockIdx.z;
    int h0 = blockIdx.y * 4, w0 = blockIdx.x * 4;
    int tid  = threadIdx.x;
    int warp = tid >> 5, lane = tid & 31;

    const float* xt = g_xt + (size_t)b * HW * CH;

    for (int task = warp; task < 144; task += 8) {
        int tap = task >> 4, pix = task & 15;
        int ph = h0 + (pix >> 2), pw = w0 + (pix & 3);
        const float* offp = g_off + ((size_t)b * HW + ph * WW + pw) * 18 + tap * 2;
        float dy = __ldg(offp), dx = __ldg(offp + 1);
        float py = (float)(ph + tap / 3 - 1) + dy;
        float px = (float)(pw + tap % 3 - 1) + dx;
        float fy = floorf(py), fx = floorf(px);
        int y0 = (int)fy, x0 = (int)fx;
        float ly = py - fy, lx = px - fx;
        float hy = 1.f - ly, hx = 1.f - lx;

        int c = lane * 2;
        float a0 = 0.f, a1 = 0.f;
        bool yok0 = (unsigned)y0       < (unsigned)HH;
        bool yok1 = (unsigned)(y0 + 1) < (unsigned)HH;
        bool xok0 = (unsigned)x0       < (unsigned)WW;
        bool xok1 = (unsigned)(x0 + 1) < (unsigned)WW;
        if (yok0 && xok0) {
            float2 v = *(const float2*)(xt + ((size_t)y0 * WW + x0) * CH + c);
            float wgt = hy * hx; a0 += wgt * v.x; a1 += wgt * v.y;
        }
        if (yok0 && xok1) {
            float2 v = *(const float2*)(xt + ((size_t)y0 * WW + x0 + 1) * CH + c);
            float wgt = hy * lx; a0 += wgt * v.x; a1 += wgt * v.y;
        }
        if (yok1 && xok0) {
            float2 v = *(const float2*)(xt + ((size_t)(y0 + 1) * WW + x0) * CH + c);
            float wgt = ly * hx; a0 += wgt * v.x; a1 += wgt * v.y;
        }
        if (yok1 && xok1) {
            float2 v = *(const float2*)(xt + ((size_t)(y0 + 1) * WW + x0 + 1) * CH + c);
            float wgt = ly * lx; a0 += wgt * v.x; a1 += wgt * v.y;
        }
        s[pix * CK + c * 9 + tap]       = a0;
        s[pix * CK + (c + 1) * 9 + tap] = a1;
    }
    __syncthreads();

    int o = tid & 63, pg = tid >> 6;
    const float* sp = s + pg * 4 * CK;
    const float* wp = g_wT + o;
    float acc0 = 0.f, acc1 = 0.f, acc2 = 0.f, acc3 = 0.f;
#pragma unroll 8
    for (int ck = 0; ck < CK; ck++) {
        float wv = __ldg(wp + (ck << 6));
        acc0 += wv * sp[ck];
        acc1 += wv * sp[CK + ck];
        acc2 += wv * sp[2 * CK + ck];
        acc3 += wv * sp[3 * CK + ck];
    }
    __syncthreads();

    // Stage outputs [o][pix] in smem (reusing s), then STG.128 4-float rows.
    float* so = s;
    so[o * 16 + pg * 4 + 0] = acc0;
    so[o * 16 + pg * 4 + 1] = acc1;
    so[o * 16 + pg * 4 + 2] = acc2;
    so[o * 16 + pg * 4 + 3] = acc3;
    __syncthreads();

    int o2 = tid >> 2, r = tid & 3;
    float4 v = *(float4*)(so + o2 * 16 + r * 4);
    *(float4*)(out + (((size_t)b * CH + o2) * HH + h0 + r) * WW + w0) = v;
}

// ---------------------------------------------------------------------------
extern "C" void kernel_launch(void* const* d_in, const int* in_sizes, int n_in,
                              void* d_out, int out_size) {
    const float* x      = (const float*)d_in[0];
    const float* w_off  = (const float*)d_in[1];
    const float* b_off  = (const float*)d_in[2];
    const float* weight = (const float*)d_in[3];
    float* out = (float*)d_out;

    k_prep_wT<<<(CK * CH + 255) / 256, 256>>>(weight);
    k_transpose<<<dim3(HW / 32, CH / 32, BATCH), dim3(32, 8)>>>(x);
    k_offconv<<<dim3(WW / 32, HH / 4, BATCH), dim3(32, 4)>>>(x, w_off, b_off);
    k_deform<<<dim3(WW / 4, HH / 4, BATCH), 256>>>(out);
}

// round 3
// speedup vs baseline: 1.0269x; 1.0269x over previous
#include <cuda_runtime.h>

#define BATCH 4
#define CH    64
#define HH    128
#define WW    128
#define HW    (HH*WW)
#define J18   18
#define CK    576   /* CH*9 */

// Device-global scratch (no allocations allowed in kernel_launch)
__device__ float g_xt[BATCH*HW*CH];    // x transposed to [b][h][w][c]
__device__ float g_off[BATCH*HW*J18];  // offsets [b][h][w][j]
__device__ float g_wT4[CK*CH];         // W repacked: [ck4][o][4]  (147 KB)

// ---------------------------------------------------------------------------
// Repack main weight: [o][c][k] -> [ck/4][o][ck%4]
// ---------------------------------------------------------------------------
__global__ void k_prep_wT(const float* __restrict__ weight) {
    int i = blockIdx.x * 256 + threadIdx.x;
    if (i >= CK * CH) return;
    int ck = i >> 6;          // 0..575
    int o  = i & 63;
    int c = ck / 9, k = ck % 9;
    g_wT4[((ck >> 2) * 64 + o) * 4 + (ck & 3)] = weight[(o * CH + c) * 9 + k];
}

// ---------------------------------------------------------------------------
// NCHW -> NHWC transpose of x
// ---------------------------------------------------------------------------
__global__ void k_transpose(const float* __restrict__ x) {
    __shared__ float t[32][33];
    int b  = blockIdx.z;
    int c0 = blockIdx.y * 32;
    int p0 = blockIdx.x * 32;
    int tx = threadIdx.x, ty = threadIdx.y;   // 32 x 8
    const float* xb = x + (size_t)b * CH * HW;
#pragma unroll
    for (int i = 0; i < 4; i++)
        t[ty + i * 8][tx] = xb[(c0 + ty + i * 8) * HW + p0 + tx];
    __syncthreads();
    float* dst = g_xt + (size_t)b * HW * CH;
#pragma unroll
    for (int i = 0; i < 4; i++)
        dst[(p0 + ty + i * 8) * CH + c0 + tx] = t[tx][ty + i * 8];
}

// ---------------------------------------------------------------------------
// Offset conv: Conv2d(64 -> 18, 3x3, pad 1) on NCHW x.
// ---------------------------------------------------------------------------
__global__ void k_offconv(const float* __restrict__ x,
                          const float* __restrict__ w_off,
                          const float* __restrict__ b_off) {
    __shared__ __align__(16) float ws[CH * 9 * 20];
    int tid = threadIdx.y * 32 + threadIdx.x;
    for (int i = tid; i < CH * 9 * J18; i += 128) {
        int j = i % 18; int t = i / 18; int tap = t % 9; int c = t / 9;
        ws[(c * 9 + tap) * 20 + j] = w_off[(j * CH + c) * 9 + tap];
    }
    __syncthreads();

    int b = blockIdx.z;
    int h = blockIdx.y * 4 + threadIdx.y;
    int w = blockIdx.x * 32 + threadIdx.x;

    float acc[18];
#pragma unroll
    for (int j = 0; j < 18; j++) acc[j] = __ldg(b_off + j);

    const float* xb = x + (size_t)b * CH * HW;
    for (int c = 0; c < CH; c++) {
        const float* xc = xb + c * HW;
#pragma unroll
        for (int r = 0; r < 3; r++) {
            int y = h + r - 1;
            if ((unsigned)y < (unsigned)HH) {
                const float* xr = xc + y * WW;
                float v0 = (w >= 1)      ? __ldg(xr + w - 1) : 0.f;
                float v1 =                 __ldg(xr + w);
                float v2 = (w < WW - 1)  ? __ldg(xr + w + 1) : 0.f;
                const float* wsr = ws + (c * 9 + r * 3) * 20;
#pragma unroll
                for (int s = 0; s < 3; s++) {
                    float val = (s == 0) ? v0 : ((s == 1) ? v1 : v2);
                    const float4* wp4 = (const float4*)(wsr + s * 20);
#pragma unroll
                    for (int q = 0; q < 4; q++) {
                        float4 wv = wp4[q];
                        acc[q * 4 + 0] += wv.x * val;
                        acc[q * 4 + 1] += wv.y * val;
                        acc[q * 4 + 2] += wv.z * val;
                        acc[q * 4 + 3] += wv.w * val;
                    }
                    acc[16] += (wsr + s * 20)[16] * val;
                    acc[17] += (wsr + s * 20)[17] * val;
                }
            }
        }
    }

    __syncthreads();
#pragma unroll
    for (int j = 0; j < 18; j++)
        ws[threadIdx.y * 576 + threadIdx.x * 18 + j] = acc[j];
    __syncthreads();
    for (int i = tid; i < 4 * 576; i += 128) {
        int row = i / 576, col = i % 576;
        int h2 = blockIdx.y * 4 + row;
        g_off[((size_t)b * HW + h2 * WW + blockIdx.x * 32) * 18 + col] = ws[row * 576 + col];
    }
}

// ---------------------------------------------------------------------------
// Deformable gather + 64x576 contraction per 4x4 pixel tile.
// smem S layout: [row pg 0..3][ck 0..575][pixel-in-row 0..3]  (float4 per ck)
// Phase 1: task=(tap, chan-half, row); lane=channel; 4 pixels/lane -> STS.128
//          (144B lane stride -> conflict-free per quarter-warp phase).
// Phase 2: thread=(o, row). W: LDG.128 [ck4][o][4]. S: broadcast LDS.v2.b64
//          giving two f32x2 pixel pairs -> fma.rn.f32x2 (2x FMA throughput).
// ---------------------------------------------------------------------------
__global__ void __launch_bounds__(256) k_deform(float* __restrict__ out) {
    __shared__ __align__(16) float s[4 * CK * 4];   // 36864 B
    int b  = blockIdx.z;
    int h0 = blockIdx.y * 4, w0 = blockIdx.x * 4;
    int tid  = threadIdx.x;
    int warp = tid >> 5, lane = tid & 31;

    const float* xt = g_xt + (size_t)b * HW * CH;

    // ---- Phase 1: 72 tasks = 9 taps x 2 chan-halves x 4 rows ----
    for (int task = warp; task < 72; task += 8) {
        int tap = task % 9;
        int rem = task / 9;            // 0..7
        int cg  = rem & 1, pg = rem >> 1;
        int c   = cg * 32 + lane;
        int ky  = tap / 3 - 1, kx = tap % 3 - 1;
        int ph  = h0 + pg;
        const float* xc = xt + c;
        const float* offrow = g_off + ((size_t)b * HW + ph * WW) * 18 + tap * 2;

        float av[4];
#pragma unroll
        for (int i = 0; i < 4; i++) {
            int pw = w0 + i;
            float dy = __ldg(offrow + pw * 18);
            float dx = __ldg(offrow + pw * 18 + 1);
            float py = (float)(ph + ky) + dy;
            float px = (float)(pw + kx) + dx;
            float fy = floorf(py), fx = floorf(px);
            int y0 = (int)fy, x0 = (int)fx;
            float ly = py - fy, lx = px - fx;
            float hy = 1.f - ly, hx = 1.f - lx;
            bool yok0 = (unsigned)y0       < (unsigned)HH;
            bool yok1 = (unsigned)(y0 + 1) < (unsigned)HH;
            bool xok0 = (unsigned)x0       < (unsigned)WW;
            bool xok1 = (unsigned)(x0 + 1) < (unsigned)WW;
            float a = 0.f;
            if (yok0 && xok0) a += hy * hx * __ldg(xc + ((size_t)y0 * WW + x0) * CH);
            if (yok0 && xok1) a += hy * lx * __ldg(xc + ((size_t)y0 * WW + x0 + 1) * CH);
            if (yok1 && xok0) a += ly * hx * __ldg(xc + ((size_t)(y0 + 1) * WW + x0) * CH);
            if (yok1 && xok1) a += ly * lx * __ldg(xc + ((size_t)(y0 + 1) * WW + x0 + 1) * CH);
            av[i] = a;
        }
        int ck = c * 9 + tap;
        float4* dst = (float4*)(s + (pg * CK + ck) * 4);
        *dst = make_float4(av[0], av[1], av[2], av[3]);
    }
    __syncthreads();

    // ---- Phase 2: thread = (o, row pg); f32x2 packed FMA ----
    int o = tid & 63, pg = tid >> 6;
    const float4* wp = (const float4*)g_wT4 + o;           // stride 64 float4s
    unsigned sbase = (unsigned)__cvta_generic_to_shared(s + pg * CK * 4);

    unsigned long long acc01 = 0ULL, acc23 = 0ULL;
#pragma unroll 4
    for (int ck4 = 0; ck4 < CK / 4; ck4++) {
        float4 wv = __ldg(wp + (ck4 << 6));
#pragma unroll
        for (int j = 0; j < 4; j++) {
            unsigned long long q01, q23, w2;
            asm volatile("ld.shared.v2.b64 {%0,%1},[%2];"
                         : "=l"(q01), "=l"(q23)
                         : "r"(sbase + (ck4 * 4 + j) * 16));
            float wj = (j == 0) ? wv.x : (j == 1) ? wv.y : (j == 2) ? wv.z : wv.w;
            asm("mov.b64 %0, {%1,%1};" : "=l"(w2) : "f"(wj));
            asm("fma.rn.f32x2 %0, %1, %2, %0;" : "+l"(acc01) : "l"(w2), "l"(q01));
            asm("fma.rn.f32x2 %0, %1, %2, %0;" : "+l"(acc23) : "l"(w2), "l"(q23));
        }
    }
    float r0, r1, r2, r3;
    asm("mov.b64 {%0,%1}, %2;" : "=f"(r0), "=f"(r1) : "l"(acc01));
    asm("mov.b64 {%0,%1}, %2;" : "=f"(r2), "=f"(r3) : "l"(acc23));
    __syncthreads();

    // Stage outputs [o][pix16] in smem (reuse s), then STG.128 rows.
    float* so = s;
    so[o * 16 + pg * 4 + 0] = r0;
    so[o * 16 + pg * 4 + 1] = r1;
    so[o * 16 + pg * 4 + 2] = r2;
    so[o * 16 + pg * 4 + 3] = r3;
    __syncthreads();

    int o2 = tid >> 2, r = tid & 3;
    float4 v = *(float4*)(so + o2 * 16 + r * 4);
    *(float4*)(out + (((size_t)b * CH + o2) * HH + h0 + r) * WW + w0) = v;
}

// ---------------------------------------------------------------------------
extern "C" void kernel_launch(void* const* d_in, const int* in_sizes, int n_in,
                              void* d_out, int out_size) {
    const float* x      = (const float*)d_in[0];
    const float* w_off  = (const float*)d_in[1];
    const float* b_off  = (const float*)d_in[2];
    const float* weight = (const float*)d_in[3];
    float* out = (float*)d_out;

    k_prep_wT<<<(CK * CH + 255) / 256, 256>>>(weight);
    k_transpose<<<dim3(HW / 32, CH / 32, BATCH), dim3(32, 8)>>>(x);
    k_offconv<<<dim3(WW / 32, HH / 4, BATCH), dim3(32, 4)>>>(x, w_off, b_off);
    k_deform<<<dim3(WW / 4, HH / 4, BATCH), 256>>>(out);
}